// round 10
// baseline (speedup 1.0000x reference)
#include <cuda_runtime.h>
#include <stdint.h>

#define NBOX   100800
#define NC     80
#define ROW    85
#define TOPK   4096
#define BINS   4096
#define CAPC   512
#define BCAP   1024
#define FCAP   2048
#define MAXDET 1000
#define CONF_T 0.4f
#define IOU_T  0.45f
#define MAXWH  7680.0f
#define BITS04 0x3ECCCCCDu
#define PADKEY 0xFFFFFFFFFFFFFFFFULL

#define K1B    296
#define K1T    256
#define K1W    (K1T / 32)
#define NWARPS (K1B * K1W)

__device__ float              g_score[NBOX];
__device__ unsigned char      g_cls[NBOX];
__device__ int                g_hist[BINS];
__device__ int                g_hist2[BINS];
__device__ int                g_tbin, g_need;
__device__ int                g_done;
__device__ int                g_ccount[NC];
__device__ unsigned long long g_ckey[NC * CAPC];
__device__ unsigned long long g_btbl[BCAP];
__device__ int                g_bcnt;
__device__ unsigned long long g_fkey[TOPK + 256];
__device__ int                g_fcnt;

// ---------------- K0: one zero kernel ----------------
__global__ void k0_zero(float* __restrict__ out) {
    int i = blockIdx.x * blockDim.x + threadIdx.x;
    int n = gridDim.x * blockDim.x;
    for (int j = i; j < BINS; j += n) { g_hist[j] = 0; g_hist2[j] = 0; }
    for (int j = i; j < NC; j += n) g_ccount[j] = 0;
    if (i == 0) { g_bcnt = 0; g_fcnt = 0; g_done = 0; }
    for (int j = i; j < MAXDET * 6; j += n) out[j] = 0.0f;
}

// ---------------- K1: warp-per-row score + argmax + hist; last block: thresh
__global__ void __launch_bounds__(K1T) k1_score(const float* __restrict__ pred) {
    __shared__ int sh[BINS];
    __shared__ int s_last;
    __shared__ int chunk2[128];
    const unsigned full = 0xffffffffu;
    int t = threadIdx.x, lane = t & 31, wid = t >> 5;
    for (int i = t; i < BINS; i += K1T) sh[i] = 0;
    __syncthreads();

    int gw = blockIdx.x * K1W + wid;
    for (int row = gw; row < NBOX; row += NWARPS) {
        const float* p = pred + (size_t)row * ROW;
        float v0 = p[lane];
        float v1 = p[32 + lane];
        float v2 = (lane < 21) ? p[64 + lane] : 0.0f;
        float obj = __shfl_sync(full, v0, 4);

        // per-lane candidates in ascending-cc order, strict > keeps first max
        float best = -1.0f; int bc = 1000;
        if (lane >= 5) {
            best = __fmul_rn(v0, obj); bc = lane - 5;         // cc 0..26
        }
        float c1 = __fmul_rn(v1, obj);                         // cc 27..58
        if (c1 > best) { best = c1; bc = 27 + lane; }
        if (lane < 21) {
            float c2 = __fmul_rn(v2, obj);                     // cc 59..79
            if (c2 > best) { best = c2; bc = 59 + lane; }
        }
        // warp merge: lexicographic (value desc, cc asc) — matches first-index argmax
        #pragma unroll
        for (int off = 16; off > 0; off >>= 1) {
            float ov = __shfl_down_sync(full, best, off);
            int   oc = __shfl_down_sync(full, bc, off);
            if (ov > best || (ov == best && oc < bc)) { best = ov; bc = oc; }
        }
        if (lane == 0) {
            g_score[row] = best;
            g_cls[row]   = (unsigned char)bc;
            if (best > CONF_T) {
                unsigned b = (__float_as_uint(best) - BITS04) >> 12;
                if (b >= BINS) b = BINS - 1;
                atomicAdd(&sh[b], 1);
            }
        }
    }
    __syncthreads();
    for (int j = t; j < BINS; j += K1T) {
        int v = sh[j];
        if (v) atomicAdd(&g_hist[j], v);
    }
    __syncthreads();

    // last-done block computes the top-K threshold (replaces k2 launch)
    if (t == 0) {
        __threadfence();
        s_last = (atomicAdd(&g_done, 1) == K1B - 1);
    }
    __syncthreads();
    if (s_last) {
        if (t < 128) {
            int s = 0;
            for (int b = t * 32; b < t * 32 + 32; b++) s += g_hist[b];
            chunk2[t] = s;
        }
        __syncthreads();
        if (t == 0) {
            int cum = 0, tb = 0, A = 0; bool found = false;
            for (int c = 127; c >= 0 && !found; c--) {
                if (cum + chunk2[c] >= TOPK) {
                    for (int b = c * 32 + 31; b >= c * 32; b--) {
                        if (cum + g_hist[b] >= TOPK) { tb = b; A = cum; found = true; break; }
                        cum += g_hist[b];
                    }
                } else cum += chunk2[c];
            }
            if (!found) { tb = 0; A = cum - g_hist[0]; }
            g_tbin = tb;
            g_need = TOPK - A;
        }
    }
}

// ---------------- K3: gather candidates ----------------
__global__ void __launch_bounds__(256) k3_gather() {
    int q = blockIdx.x * 256 + threadIdx.x;
    if (q * 4 >= NBOX) return;
    float4 s4 = *(const float4*)(g_score + q * 4);
    int tb = g_tbin;
    float sv[4] = { s4.x, s4.y, s4.z, s4.w };
    #pragma unroll
    for (int u = 0; u < 4; u++) {
        float s = sv[u];
        if (s > CONF_T) {
            unsigned sb = __float_as_uint(s);
            unsigned b  = (sb - BITS04) >> 12;
            if (b >= BINS) b = BINS - 1;
            if ((int)b >= tb) {
                int i = q * 4 + u;
                unsigned long long key = ((unsigned long long)(~sb) << 32) | (unsigned)i;
                if ((int)b > tb) {
                    int c = g_cls[i];
                    int p = atomicAdd(&g_ccount[c], 1);
                    if (p < CAPC) g_ckey[c * CAPC + p] = key;
                } else {
                    int p = atomicAdd(&g_bcnt, 1);
                    if (p < BCAP) g_btbl[p] = key;
                }
            }
        }
    }
}

// ---------------- K5: per-class sort + greedy NMS ----------------
__global__ void __launch_bounds__(256) k5_nms(const float* __restrict__ pred) {
    __shared__ unsigned long long skey[CAPC];
    __shared__ unsigned long long sbt[BCAP];
    __shared__ float sx1[CAPC], sy1[CAPC], sx2[CAPC], sy2[CAPC], sar[CAPC];
    __shared__ unsigned char skeep[CAPC];
    __shared__ int s_extra;

    const unsigned full = 0xffffffffu;
    int t = threadIdx.x, lane = t & 31;
    int myc = blockIdx.x;
    int cnt = min(g_ccount[myc], CAPC);
    int m = min(g_bcnt, BCAP);
    int need = g_need;

    if (t == 0) s_extra = 0;
    for (int i = t; i < m; i += 256) sbt[i] = g_btbl[i];
    __syncthreads();

    for (int e = t; e < m; e += 256) {
        unsigned long long k = sbt[e];
        int r = 0;
        for (int j = 0; j < m; j++) r += (sbt[j] < k);
        if (r < need) {
            unsigned idx = (unsigned)k;
            if (g_cls[idx] == (unsigned char)myc) {
                int p = atomicAdd(&s_extra, 1);
                if (cnt + p < CAPC) skey[cnt + p] = k;
            }
        }
    }
    for (int i = t; i < cnt; i += 256) skey[i] = g_ckey[myc * CAPC + i];
    __syncthreads();

    int tot = cnt + s_extra;
    if (tot > CAPC) tot = CAPC;
    for (int i = t; i < CAPC; i += 256) if (i >= tot) skey[i] = PADKEY;
    __syncthreads();

    for (int k = 2; k <= CAPC; k <<= 1)
        for (int j = k >> 1; j > 0; j >>= 1) {
            for (int i = t; i < CAPC; i += 256) {
                int l = i ^ j;
                if (l > i) {
                    unsigned long long a = skey[i], b = skey[l];
                    bool up = ((i & k) == 0);
                    if ((a > b) == up) { skey[i] = b; skey[l] = a; }
                }
            }
            __syncthreads();
        }

    float off = __fmul_rn((float)myc, MAXWH);
    for (int i = t; i < tot; i += 256) {
        unsigned idx = (unsigned)skey[i];
        const float* p = pred + (size_t)idx * ROW;
        float x = p[0], y = p[1], w = p[2], h = p[3];
        float hw = __fmul_rn(w, 0.5f), hh = __fmul_rn(h, 0.5f);
        float b0 = __fsub_rn(x, hw), b1 = __fsub_rn(y, hh);
        float b2 = __fadd_rn(x, hw), b3 = __fadd_rn(y, hh);
        float q0 = __fadd_rn(b0, off), q1 = __fadd_rn(b1, off);
        float q2 = __fadd_rn(b2, off), q3 = __fadd_rn(b3, off);
        sx1[i] = q0; sy1[i] = q1; sx2[i] = q2; sy2[i] = q3;
        sar[i] = __fmul_rn(__fsub_rn(q2, q0), __fsub_rn(q3, q1));
        skeep[i] = 1;
    }
    __syncthreads();

    if (t < 32) {
        for (int tt = 0; tt < tot; tt++) {
            if (skeep[tt]) {
                float x1 = sx1[tt], y1 = sy1[tt], x2 = sx2[tt], y2 = sy2[tt], a = sar[tt];
                for (int j = tt + 1 + lane; j < tot; j += 32) {
                    float ltx = fmaxf(sx1[j], x1);
                    float lty = fmaxf(sy1[j], y1);
                    float rbx = fminf(sx2[j], x2);
                    float rby = fminf(sy2[j], y2);
                    float ww  = fmaxf(__fsub_rn(rbx, ltx), 0.0f);
                    float hh  = fmaxf(__fsub_rn(rby, lty), 0.0f);
                    float inter = __fmul_rn(ww, hh);
                    float den = __fadd_rn(__fsub_rn(__fadd_rn(a, sar[j]), inter), 1e-9f);
                    if (__fdiv_rn(inter, den) > IOU_T) skeep[j] = 0;
                }
            }
            __syncwarp(full);
        }
    }
    __syncthreads();

    for (int i = t; i < CAPC; i += 256) {
        bool kp = (i < tot) && skeep[i];
        unsigned msk = __ballot_sync(full, kp);
        int base = 0;
        if (lane == 0 && msk) base = atomicAdd(&g_fcnt, __popc(msk));
        base = __shfl_sync(full, base, 0);
        if (kp) {
            g_fkey[base + __popc(msk & ((1u << lane) - 1u))] = skey[i];
            unsigned sb = ~(unsigned)(skey[i] >> 32);
            unsigned b = (sb - BITS04) >> 12;
            if (b >= BINS) b = BINS - 1;
            atomicAdd(&g_hist2[b], 1);
        }
    }
}

// ---------------- K8: threshold + rank-selection (no sort) + write ---------
__global__ void __launch_bounds__(1024) k8_final(const float* __restrict__ pred,
                                                 float* __restrict__ out) {
    __shared__ unsigned long long fk[FCAP];
    __shared__ int chunk[128];
    __shared__ int s_T2, s_cnt;
    int t = threadIdx.x, lane = t & 31;

    if (t < 128) {
        int s = 0;
        for (int b = t * 32; b < t * 32 + 32; b++) s += g_hist2[b];
        chunk[t] = s;
    }
    if (t == 0) s_cnt = 0;
    __syncthreads();
    if (t == 0) {
        int cum = 0, T2 = 0; bool found = false;
        for (int c = 127; c >= 0 && !found; c--) {
            if (cum + chunk[c] >= MAXDET) {
                for (int b = c * 32 + 31; b >= c * 32; b--) {
                    if (cum + g_hist2[b] >= MAXDET) { T2 = b; found = true; break; }
                    cum += g_hist2[b];
                }
            } else cum += chunk[c];
        }
        s_T2 = found ? T2 : 0;
    }
    __syncthreads();

    // gather kept keys above the final threshold bin
    int K = min(g_fcnt, TOPK + 256);
    int T2 = s_T2;
    int Kr = (K + 31) & ~31;
    for (int i = t; i < Kr; i += 1024) {
        bool take = false;
        unsigned long long key = PADKEY;
        if (i < K) {
            key = g_fkey[i];
            unsigned sb = ~(unsigned)(key >> 32);
            unsigned b = (sb - BITS04) >> 12;
            if (b >= BINS) b = BINS - 1;
            take = ((int)b >= T2);
        }
        unsigned msk = __ballot_sync(0xffffffffu, take);
        int base = 0;
        if (lane == 0 && msk) base = atomicAdd(&s_cnt, __popc(msk));
        base = __shfl_sync(0xffffffffu, base, 0);
        if (take) {
            int p = base + __popc(msk & ((1u << lane) - 1u));
            if (p < FCAP) fk[p] = key;
        }
    }
    __syncthreads();

    // exact rank per key (keys unique) == position after ascending sort
    int m2 = min(s_cnt, FCAP);
    for (int i = t; i < m2; i += 1024) {
        unsigned long long key = fk[i];
        int r = 0;
        for (int j = 0; j < m2; j++) r += (fk[j] < key);   // smem broadcast reads
        if (r < MAXDET) {
            unsigned idx = (unsigned)key;
            float s = __uint_as_float(~(unsigned)(key >> 32));
            const float* p = pred + (size_t)idx * ROW;
            float x = p[0], y = p[1], w = p[2], h = p[3];
            float hw = __fmul_rn(w, 0.5f), hh = __fmul_rn(h, 0.5f);
            out[r * 6 + 0] = __fsub_rn(x, hw);
            out[r * 6 + 1] = __fsub_rn(y, hh);
            out[r * 6 + 2] = __fadd_rn(x, hw);
            out[r * 6 + 3] = __fadd_rn(y, hh);
            out[r * 6 + 4] = s;
            out[r * 6 + 5] = (float)g_cls[idx];
        }
    }
}

extern "C" void kernel_launch(void* const* d_in, const int* in_sizes, int n_in,
                              void* d_out, int out_size) {
    (void)in_sizes; (void)n_in; (void)out_size;
    const float* pred = (const float*)d_in[0];
    float* out = (float*)d_out;

    k0_zero<<<24, 256>>>(out);
    k1_score<<<K1B, K1T>>>(pred);
    k3_gather<<<(NBOX / 4 + 255) / 256, 256>>>();
    k5_nms<<<NC, 256>>>(pred);
    k8_final<<<1, 1024>>>(pred, out);
}

// round 11
// speedup vs baseline: 1.2743x; 1.2743x over previous
#include <cuda_runtime.h>
#include <stdint.h>

#define NBOX   100800
#define NC     80
#define ROW    85
#define TOPK   4096
#define BINS   4096
#define CAPC   512
#define BCAP   1024
#define FCAP   2048
#define MAXDET 1000
#define CONF_T 0.4f
#define IOU_T  0.45f
#define MAXWH  7680.0f
#define BITS04 0x3ECCCCCDu
#define PADKEY 0xFFFFFFFFFFFFFFFFULL

#define K1B    296
#define K1T    256
#define CROWS  256
#define NCHUNK ((NBOX + CROWS - 1) / CROWS)
#define K1SMEM ((CROWS * ROW + BINS) * 4)        // 103424 B -> 2 blocks/SM

// k5 dynamic smem layout
#define SM5_SKEY 0
#define SM5_SBT  4096
#define SM5_SX1  12288
#define SM5_SY1  14336
#define SM5_SX2  16384
#define SM5_SY2  18432
#define SM5_SAR  20480
#define SM5_SUP  22528                            // 512 rows x 8 u64 = 32768 B
#define K5SMEM   (SM5_SUP + CAPC * 8 * 8)         // 55296 B

__device__ float              g_score[NBOX];
__device__ unsigned char      g_cls[NBOX];
__device__ int                g_hist[BINS];
__device__ int                g_hist2[BINS];
__device__ int                g_tbin, g_need;
__device__ int                g_done;
__device__ int                g_ccount[NC];
__device__ unsigned long long g_ckey[NC * CAPC];
__device__ unsigned long long g_btbl[BCAP];
__device__ int                g_bcnt;
__device__ unsigned long long g_fkey[TOPK + 256];
__device__ int                g_fcnt;

// ---------------- K0: zero scratch + output ----------------
__global__ void k0_zero(float* __restrict__ out) {
    int i = blockIdx.x * blockDim.x + threadIdx.x;
    int n = gridDim.x * blockDim.x;
    for (int j = i; j < BINS; j += n) { g_hist[j] = 0; g_hist2[j] = 0; }
    for (int j = i; j < NC; j += n) g_ccount[j] = 0;
    if (i == 0) { g_bcnt = 0; g_fcnt = 0; g_done = 0; }
    for (int j = i; j < MAXDET * 6; j += n) out[j] = 0.0f;
}

// ---------------- K1: staged score+argmax+hist; last block: threshold -------
__global__ void __launch_bounds__(K1T) k1_score(const float* __restrict__ pred) {
    extern __shared__ float smem_f[];
    float* srow = smem_f;                          // CROWS*ROW floats
    int*   sh   = (int*)(smem_f + CROWS * ROW);    // BINS ints
    __shared__ int s_last;
    __shared__ int chunk2[128];
    int t = threadIdx.x;
    for (int i = t; i < BINS; i += K1T) sh[i] = 0;
    __syncthreads();

    for (int c = blockIdx.x; c < NCHUNK; c += K1B) {
        int b0 = c * CROWS;
        int nrows = NBOX - b0; if (nrows > CROWS) nrows = CROWS;
        int nf4 = (nrows * ROW) >> 2;              // nrows % 4 == 0 -> exact
        const float4* src = (const float4*)(pred + (size_t)b0 * ROW);
        float4* dst = (float4*)srow;
        #pragma unroll 4
        for (int i = t; i < nf4; i += K1T) dst[i] = src[i];
        __syncthreads();

        if (t < nrows) {
            const float* p = srow + t * ROW;
            float obj = p[4];
            float best = -1.0f; int bc = 0;
            #pragma unroll
            for (int cc = 0; cc < NC; cc++) {
                float v = __fmul_rn(p[5 + cc], obj);
                if (v > best) { best = v; bc = cc; }
            }
            int gi = b0 + t;
            g_score[gi] = best;
            g_cls[gi]   = (unsigned char)bc;
            if (best > CONF_T) {
                unsigned b = (__float_as_uint(best) - BITS04) >> 12;
                if (b >= BINS) b = BINS - 1;
                atomicAdd(&sh[b], 1);
            }
        }
        __syncthreads();
    }
    for (int j = t; j < BINS; j += K1T) {
        int v = sh[j];
        if (v) atomicAdd(&g_hist[j], v);
    }
    __syncthreads();

    if (t == 0) {
        __threadfence();
        s_last = (atomicAdd(&g_done, 1) == K1B - 1);
    }
    __syncthreads();
    if (s_last) {
        if (t < 128) {
            int s = 0;
            for (int b = t * 32; b < t * 32 + 32; b++) s += g_hist[b];
            chunk2[t] = s;
        }
        __syncthreads();
        if (t == 0) {
            int cum = 0, tb = 0, A = 0; bool found = false;
            for (int c = 127; c >= 0 && !found; c--) {
                if (cum + chunk2[c] >= TOPK) {
                    for (int b = c * 32 + 31; b >= c * 32; b--) {
                        if (cum + g_hist[b] >= TOPK) { tb = b; A = cum; found = true; break; }
                        cum += g_hist[b];
                    }
                } else cum += chunk2[c];
            }
            if (!found) { tb = 0; A = cum - g_hist[0]; }
            g_tbin = tb;
            g_need = TOPK - A;
        }
    }
}

// ---------------- K3: gather candidates ----------------
__global__ void __launch_bounds__(256) k3_gather() {
    int q = blockIdx.x * 256 + threadIdx.x;
    if (q * 4 >= NBOX) return;
    float4 s4 = *(const float4*)(g_score + q * 4);
    int tb = g_tbin;
    float sv[4] = { s4.x, s4.y, s4.z, s4.w };
    #pragma unroll
    for (int u = 0; u < 4; u++) {
        float s = sv[u];
        if (s > CONF_T) {
            unsigned sb = __float_as_uint(s);
            unsigned b  = (sb - BITS04) >> 12;
            if (b >= BINS) b = BINS - 1;
            if ((int)b >= tb) {
                int i = q * 4 + u;
                unsigned long long key = ((unsigned long long)(~sb) << 32) | (unsigned)i;
                if ((int)b > tb) {
                    int c = g_cls[i];
                    int p = atomicAdd(&g_ccount[c], 1);
                    if (p < CAPC) g_ckey[c * CAPC + p] = key;
                } else {
                    int p = atomicAdd(&g_bcnt, 1);
                    if (p < BCAP) g_btbl[p] = key;
                }
            }
        }
    }
}

// ---------------- K5: sized sort + parallel IoU matrix + bit greedy --------
__global__ void __launch_bounds__(256) k5_nms(const float* __restrict__ pred) {
    extern __shared__ char sm5[];
    unsigned long long* skey = (unsigned long long*)(sm5 + SM5_SKEY);
    unsigned long long* sbt  = (unsigned long long*)(sm5 + SM5_SBT);
    float* sx1 = (float*)(sm5 + SM5_SX1);
    float* sy1 = (float*)(sm5 + SM5_SY1);
    float* sx2 = (float*)(sm5 + SM5_SX2);
    float* sy2 = (float*)(sm5 + SM5_SY2);
    float* sar = (float*)(sm5 + SM5_SAR);
    unsigned long long* sup = (unsigned long long*)(sm5 + SM5_SUP);  // [CAPC][8]
    __shared__ int s_extra;
    __shared__ unsigned long long s_keep[8];

    const unsigned full = 0xffffffffu;
    int t = threadIdx.x, lane = t & 31;
    int myc = blockIdx.x;
    int cnt = min(g_ccount[myc], CAPC);
    int m = min(g_bcnt, BCAP);
    int need = g_need;

    if (t == 0) s_extra = 0;
    for (int i = t; i < m; i += 256) sbt[i] = g_btbl[i];
    __syncthreads();

    // boundary-bin members: exact rank, top-`need` join candidates
    for (int e = t; e < m; e += 256) {
        unsigned long long k = sbt[e];
        int r = 0;
        for (int j = 0; j < m; j++) r += (sbt[j] < k);
        if (r < need) {
            unsigned idx = (unsigned)k;
            if (g_cls[idx] == (unsigned char)myc) {
                int p = atomicAdd(&s_extra, 1);
                if (cnt + p < CAPC) skey[cnt + p] = k;
            }
        }
    }
    for (int i = t; i < cnt; i += 256) skey[i] = g_ckey[myc * CAPC + i];
    __syncthreads();

    int tot = cnt + s_extra;
    if (tot > CAPC) tot = CAPC;
    int n2 = 2; while (n2 < tot) n2 <<= 1;         // sort only what exists
    for (int i = t; i < n2; i += 256) if (i >= tot) skey[i] = PADKEY;
    __syncthreads();

    for (int k = 2; k <= n2; k <<= 1)
        for (int j = k >> 1; j > 0; j >>= 1) {
            for (int i = t; i < n2; i += 256) {
                int l = i ^ j;
                if (l > i) {
                    unsigned long long a = skey[i], b = skey[l];
                    bool up = ((i & k) == 0);
                    if ((a > b) == up) { skey[i] = b; skey[l] = a; }
                }
            }
            __syncthreads();
        }

    // offsetted coords (exact ref op order)
    float off = __fmul_rn((float)myc, MAXWH);
    for (int i = t; i < tot; i += 256) {
        unsigned idx = (unsigned)skey[i];
        const float* p = pred + (size_t)idx * ROW;
        float x = p[0], y = p[1], w = p[2], h = p[3];
        float hw = __fmul_rn(w, 0.5f), hh = __fmul_rn(h, 0.5f);
        float b0 = __fsub_rn(x, hw), b1 = __fsub_rn(y, hh);
        float b2 = __fadd_rn(x, hw), b3 = __fadd_rn(y, hh);
        float q0 = __fadd_rn(b0, off), q1 = __fadd_rn(b1, off);
        float q2 = __fadd_rn(b2, off), q3 = __fadd_rn(b3, off);
        sx1[i] = q0; sy1[i] = q1; sx2[i] = q2; sy2[i] = q3;
        sar[i] = __fmul_rn(__fsub_rn(q2, q0), __fsub_rn(q3, q1));
    }
    for (int i = t; i < tot * 8; i += 256) sup[i] = 0;
    __syncthreads();

    // parallel pairwise suppression matrix: row i gets bit j for j>i, iou>thr
    int tt2 = tot * tot;
    for (int idx = t; idx < tt2; idx += 256) {
        int i = idx / tot;
        int j = idx - i * tot;
        if (j > i) {
            float ltx = fmaxf(sx1[j], sx1[i]);
            float lty = fmaxf(sy1[j], sy1[i]);
            float rbx = fminf(sx2[j], sx2[i]);
            float rby = fminf(sy2[j], sy2[i]);
            float ww  = fmaxf(__fsub_rn(rbx, ltx), 0.0f);
            float hh  = fmaxf(__fsub_rn(rby, lty), 0.0f);
            float inter = __fmul_rn(ww, hh);
            float den = __fadd_rn(__fsub_rn(__fadd_rn(sar[i], sar[j]), inter), 1e-9f);
            if (__fdiv_rn(inter, den) > IOU_T)
                atomicOr(&sup[i * 8 + (j >> 6)], 1ULL << (j & 63));
        }
    }
    __syncthreads();

    // greedy as bit recurrence (exactly ref's fori_loop over sup_mat)
    if (t == 0) {
        unsigned long long keep[8];
        #pragma unroll
        for (int w = 0; w < 8; w++) {
            int lo = w * 64;
            keep[w] = (tot >= lo + 64) ? ~0ULL
                    : (tot <= lo ? 0ULL : ((1ULL << (tot - lo)) - 1ULL));
        }
        for (int i = 0; i < tot; i++) {
            if ((keep[i >> 6] >> (i & 63)) & 1ULL) {
                #pragma unroll
                for (int w = 0; w < 8; w++) keep[w] &= ~sup[i * 8 + w];
            }
        }
        #pragma unroll
        for (int w = 0; w < 8; w++) s_keep[w] = keep[w];
    }
    __syncthreads();

    // push kept keys + kept-score histogram
    for (int i = t; i < CAPC; i += 256) {
        bool kp = (i < tot) && ((s_keep[i >> 6] >> (i & 63)) & 1ULL);
        unsigned msk = __ballot_sync(full, kp);
        int base = 0;
        if (lane == 0 && msk) base = atomicAdd(&g_fcnt, __popc(msk));
        base = __shfl_sync(full, base, 0);
        if (kp) {
            g_fkey[base + __popc(msk & ((1u << lane) - 1u))] = skey[i];
            unsigned sb = ~(unsigned)(skey[i] >> 32);
            unsigned b = (sb - BITS04) >> 12;
            if (b >= BINS) b = BINS - 1;
            atomicAdd(&g_hist2[b], 1);
        }
    }
}

// ---------------- K8: threshold + rank-selection + write ----------------
__global__ void __launch_bounds__(1024) k8_final(const float* __restrict__ pred,
                                                 float* __restrict__ out) {
    __shared__ unsigned long long fk[FCAP];
    __shared__ int chunk[128];
    __shared__ int s_T2, s_cnt;
    int t = threadIdx.x, lane = t & 31;

    if (t < 128) {
        int s = 0;
        for (int b = t * 32; b < t * 32 + 32; b++) s += g_hist2[b];
        chunk[t] = s;
    }
    if (t == 0) s_cnt = 0;
    __syncthreads();
    if (t == 0) {
        int cum = 0, T2 = 0; bool found = false;
        for (int c = 127; c >= 0 && !found; c--) {
            if (cum + chunk[c] >= MAXDET) {
                for (int b = c * 32 + 31; b >= c * 32; b--) {
                    if (cum + g_hist2[b] >= MAXDET) { T2 = b; found = true; break; }
                    cum += g_hist2[b];
                }
            } else cum += chunk[c];
        }
        s_T2 = found ? T2 : 0;
    }
    __syncthreads();

    int K = min(g_fcnt, TOPK + 256);
    int T2 = s_T2;
    int Kr = (K + 31) & ~31;
    for (int i = t; i < Kr; i += 1024) {
        bool take = false;
        unsigned long long key = PADKEY;
        if (i < K) {
            key = g_fkey[i];
            unsigned sb = ~(unsigned)(key >> 32);
            unsigned b = (sb - BITS04) >> 12;
            if (b >= BINS) b = BINS - 1;
            take = ((int)b >= T2);
        }
        unsigned msk = __ballot_sync(0xffffffffu, take);
        int base = 0;
        if (lane == 0 && msk) base = atomicAdd(&s_cnt, __popc(msk));
        base = __shfl_sync(0xffffffffu, base, 0);
        if (take) {
            int p = base + __popc(msk & ((1u << lane) - 1u));
            if (p < FCAP) fk[p] = key;
        }
    }
    __syncthreads();

    int m2 = min(s_cnt, FCAP);
    for (int i = t; i < m2; i += 1024) {
        unsigned long long key = fk[i];
        int r = 0;
        for (int j = 0; j < m2; j++) r += (fk[j] < key);   // exact rank, unique keys
        if (r < MAXDET) {
            unsigned idx = (unsigned)key;
            float s = __uint_as_float(~(unsigned)(key >> 32));
            const float* p = pred + (size_t)idx * ROW;
            float x = p[0], y = p[1], w = p[2], h = p[3];
            float hw = __fmul_rn(w, 0.5f), hh = __fmul_rn(h, 0.5f);
            out[r * 6 + 0] = __fsub_rn(x, hw);
            out[r * 6 + 1] = __fsub_rn(y, hh);
            out[r * 6 + 2] = __fadd_rn(x, hw);
            out[r * 6 + 3] = __fadd_rn(y, hh);
            out[r * 6 + 4] = s;
            out[r * 6 + 5] = (float)g_cls[idx];
        }
    }
}

extern "C" void kernel_launch(void* const* d_in, const int* in_sizes, int n_in,
                              void* d_out, int out_size) {
    (void)in_sizes; (void)n_in; (void)out_size;
    const float* pred = (const float*)d_in[0];
    float* out = (float*)d_out;

    static int configured = 0;
    if (!configured) {
        cudaFuncSetAttribute(k1_score, cudaFuncAttributeMaxDynamicSharedMemorySize,
                             K1SMEM);
        cudaFuncSetAttribute(k5_nms, cudaFuncAttributeMaxDynamicSharedMemorySize,
                             K5SMEM);
        configured = 1;
    }

    k0_zero<<<24, 256>>>(out);
    k1_score<<<K1B, K1T, K1SMEM>>>(pred);
    k3_gather<<<(NBOX / 4 + 255) / 256, 256>>>();
    k5_nms<<<NC, 256, K5SMEM>>>(pred);
    k8_final<<<1, 1024>>>(pred, out);
}

// round 12
// speedup vs baseline: 1.3131x; 1.0304x over previous
#include <cuda_runtime.h>
#include <stdint.h>

#define NBOX   100800
#define NC     80
#define ROW    85
#define TOPK   4096
#define BINS   4096
#define CAPC   512
#define BCAP   1024
#define FCAP   2048
#define MAXDET 1000
#define CONF_T 0.4f
#define IOU_T  0.45f
#define MAXWH  7680.0f
#define BITS04 0x3ECCCCCDu
#define PADKEY 0xFFFFFFFFFFFFFFFFULL

#define K1B    296
#define K1T    256
#define CROWS  256
#define NCHUNK ((NBOX + CROWS - 1) / CROWS)
#define K1SMEM ((CROWS * ROW + BINS) * 4)        // 103424 B -> 2 blocks/SM

// k5 dynamic smem layout (bytes)
#define SM5_RAW  0                                // CAPC u64
#define SM5_KEY  4096                             // CAPC u64 (rank-ordered)
#define SM5_SBT  8192                             // BCAP u64
#define SM5_SX1  16384
#define SM5_SY1  18432
#define SM5_SX2  20480
#define SM5_SY2  22528
#define SM5_SAR  24576
#define SM5_SUP  26624                            // u32 [CAPC][16]
#define K5SMEM   (SM5_SUP + CAPC * 16 * 4)        // 59392 B

__device__ float              g_score[NBOX];
__device__ unsigned char      g_cls[NBOX];
__device__ int                g_hist[BINS];
__device__ int                g_hist2[BINS];
__device__ int                g_tbin, g_need;
__device__ int                g_done;
__device__ int                g_ccount[NC];
__device__ unsigned long long g_ckey[NC * CAPC];
__device__ unsigned long long g_btbl[BCAP];
__device__ int                g_bcnt;
__device__ unsigned long long g_fkey[TOPK + 256];
__device__ int                g_fcnt;

// ---------------- K0: zero scratch + output ----------------
__global__ void k0_zero(float* __restrict__ out) {
    int i = blockIdx.x * blockDim.x + threadIdx.x;
    int n = gridDim.x * blockDim.x;
    for (int j = i; j < BINS; j += n) { g_hist[j] = 0; g_hist2[j] = 0; }
    for (int j = i; j < NC; j += n) g_ccount[j] = 0;
    if (i == 0) { g_bcnt = 0; g_fcnt = 0; g_done = 0; }
    for (int j = i; j < MAXDET * 6; j += n) out[j] = 0.0f;
}

// ---------------- K1: staged score+argmax+hist; last block: threshold -------
__global__ void __launch_bounds__(K1T) k1_score(const float* __restrict__ pred) {
    extern __shared__ float smem_f[];
    float* srow = smem_f;                          // CROWS*ROW floats
    int*   sh   = (int*)(smem_f + CROWS * ROW);    // BINS ints
    __shared__ int s_last;
    __shared__ int chunk2[128];
    int t = threadIdx.x;
    for (int i = t; i < BINS; i += K1T) sh[i] = 0;
    __syncthreads();

    for (int c = blockIdx.x; c < NCHUNK; c += K1B) {
        int b0 = c * CROWS;
        int nrows = NBOX - b0; if (nrows > CROWS) nrows = CROWS;
        int nf4 = (nrows * ROW) >> 2;
        const float4* src = (const float4*)(pred + (size_t)b0 * ROW);
        float4* dst = (float4*)srow;
        #pragma unroll 4
        for (int i = t; i < nf4; i += K1T) dst[i] = src[i];
        __syncthreads();

        if (t < nrows) {
            const float* p = srow + t * ROW;
            float obj = p[4];
            float best = -1.0f; int bc = 0;
            #pragma unroll
            for (int cc = 0; cc < NC; cc++) {
                float v = __fmul_rn(p[5 + cc], obj);
                if (v > best) { best = v; bc = cc; }
            }
            int gi = b0 + t;
            g_score[gi] = best;
            g_cls[gi]   = (unsigned char)bc;
            if (best > CONF_T) {
                unsigned b = (__float_as_uint(best) - BITS04) >> 12;
                if (b >= BINS) b = BINS - 1;
                atomicAdd(&sh[b], 1);
            }
        }
        __syncthreads();
    }
    for (int j = t; j < BINS; j += K1T) {
        int v = sh[j];
        if (v) atomicAdd(&g_hist[j], v);
    }
    __syncthreads();

    if (t == 0) {
        __threadfence();
        s_last = (atomicAdd(&g_done, 1) == K1B - 1);
    }
    __syncthreads();
    if (s_last) {
        if (t < 128) {
            int s = 0;
            for (int b = t * 32; b < t * 32 + 32; b++) s += g_hist[b];
            chunk2[t] = s;
        }
        __syncthreads();
        if (t == 0) {
            int cum = 0, tb = 0, A = 0; bool found = false;
            for (int c = 127; c >= 0 && !found; c--) {
                if (cum + chunk2[c] >= TOPK) {
                    for (int b = c * 32 + 31; b >= c * 32; b--) {
                        if (cum + g_hist[b] >= TOPK) { tb = b; A = cum; found = true; break; }
                        cum += g_hist[b];
                    }
                } else cum += chunk2[c];
            }
            if (!found) { tb = 0; A = cum - g_hist[0]; }
            g_tbin = tb;
            g_need = TOPK - A;
        }
    }
}

// ---------------- K3: gather candidates ----------------
__global__ void __launch_bounds__(256) k3_gather() {
    int q = blockIdx.x * 256 + threadIdx.x;
    if (q * 4 >= NBOX) return;
    float4 s4 = *(const float4*)(g_score + q * 4);
    int tb = g_tbin;
    float sv[4] = { s4.x, s4.y, s4.z, s4.w };
    #pragma unroll
    for (int u = 0; u < 4; u++) {
        float s = sv[u];
        if (s > CONF_T) {
            unsigned sb = __float_as_uint(s);
            unsigned b  = (sb - BITS04) >> 12;
            if (b >= BINS) b = BINS - 1;
            if ((int)b >= tb) {
                int i = q * 4 + u;
                unsigned long long key = ((unsigned long long)(~sb) << 32) | (unsigned)i;
                if ((int)b > tb) {
                    int c = g_cls[i];
                    int p = atomicAdd(&g_ccount[c], 1);
                    if (p < CAPC) g_ckey[c * CAPC + p] = key;
                } else {
                    int p = atomicAdd(&g_bcnt, 1);
                    if (p < BCAP) g_btbl[p] = key;
                }
            }
        }
    }
}

// ---------------- K5: rank-scatter + ballot matrix + bit greedy (~7 barriers)
__global__ void __launch_bounds__(256) k5_nms(const float* __restrict__ pred) {
    extern __shared__ char sm5[];
    unsigned long long* raw  = (unsigned long long*)(sm5 + SM5_RAW);
    unsigned long long* skey = (unsigned long long*)(sm5 + SM5_KEY);
    unsigned long long* sbt  = (unsigned long long*)(sm5 + SM5_SBT);
    float* sx1 = (float*)(sm5 + SM5_SX1);
    float* sy1 = (float*)(sm5 + SM5_SY1);
    float* sx2 = (float*)(sm5 + SM5_SX2);
    float* sy2 = (float*)(sm5 + SM5_SY2);
    float* sar = (float*)(sm5 + SM5_SAR);
    unsigned* sup = (unsigned*)(sm5 + SM5_SUP);   // [CAPC][16] u32 words
    __shared__ int s_extra;
    __shared__ unsigned s_keep[16];

    const unsigned full = 0xffffffffu;
    int t = threadIdx.x, lane = t & 31, wid = t >> 5;
    int myc = blockIdx.x;
    int cnt = min(g_ccount[myc], CAPC);
    int m = min(g_bcnt, BCAP);
    int need = g_need;

    if (t == 0) s_extra = 0;
    for (int i = t; i < m; i += 256) sbt[i] = g_btbl[i];
    for (int i = t; i < cnt; i += 256) raw[i] = g_ckey[myc * CAPC + i];
    __syncthreads();                                              // B1

    // boundary-bin members: exact rank among boundary table, top-`need` join
    for (int e = t; e < m; e += 256) {
        unsigned long long k = sbt[e];
        int r = 0;
        for (int j = 0; j < m; j++) r += (sbt[j] < k);
        if (r < need) {
            unsigned idx = (unsigned)k;
            if (g_cls[idx] == (unsigned char)myc) {
                int p = atomicAdd(&s_extra, 1);
                if (cnt + p < CAPC) raw[cnt + p] = k;
            }
        }
    }
    __syncthreads();                                              // B2

    int tot = cnt + s_extra;
    if (tot > CAPC) tot = CAPC;
    float off = __fmul_rn((float)myc, MAXWH);

    // rank (keys unique) -> scatter key + coords to sorted position
    for (int i = t; i < tot; i += 256) {
        unsigned long long k = raw[i];
        int r = 0;
        for (int j = 0; j < tot; j++) r += (raw[j] < k);
        skey[r] = k;
        unsigned idx = (unsigned)k;
        const float* p = pred + (size_t)idx * ROW;
        float x = p[0], y = p[1], w = p[2], h = p[3];
        float hw = __fmul_rn(w, 0.5f), hh = __fmul_rn(h, 0.5f);
        float b0 = __fsub_rn(x, hw), b1 = __fsub_rn(y, hh);
        float b2 = __fadd_rn(x, hw), b3 = __fadd_rn(y, hh);
        float q0 = __fadd_rn(b0, off), q1 = __fadd_rn(b1, off);
        float q2 = __fadd_rn(b2, off), q3 = __fadd_rn(b3, off);
        sx1[r] = q0; sy1[r] = q1; sx2[r] = q2; sy2[r] = q3;
        sar[r] = __fmul_rn(__fsub_rn(q2, q0), __fsub_rn(q3, q1));
    }
    __syncthreads();                                              // B3

    // suppression matrix via warp ballots: row r, 32-wide column chunks
    int nw = (tot + 31) >> 5;
    for (int r = wid; r < tot; r += 8) {
        float x1 = sx1[r], y1 = sy1[r], x2 = sx2[r], y2 = sy2[r], a = sar[r];
        for (int w = 0; w < nw; w++) {
            int j = w * 32 + lane;
            bool s = false;
            if (j < tot && j > r) {
                float ltx = fmaxf(sx1[j], x1);
                float lty = fmaxf(sy1[j], y1);
                float rbx = fminf(sx2[j], x2);
                float rby = fminf(sy2[j], y2);
                float ww  = fmaxf(__fsub_rn(rbx, ltx), 0.0f);
                float hh  = fmaxf(__fsub_rn(rby, lty), 0.0f);
                float inter = __fmul_rn(ww, hh);
                float den = __fadd_rn(__fsub_rn(__fadd_rn(a, sar[j]), inter), 1e-9f);
                s = __fdiv_rn(inter, den) > IOU_T;
            }
            unsigned msk = __ballot_sync(full, s);
            if (lane == 0) sup[r * 16 + w] = msk;
        }
    }
    __syncthreads();                                              // B4

    // greedy bit recurrence (== reference fori_loop over sup_mat)
    if (t == 0) {
        unsigned keep[16];
        #pragma unroll
        for (int w = 0; w < 16; w++) {
            int lo = w * 32;
            keep[w] = (tot >= lo + 32) ? 0xffffffffu
                    : (tot <= lo ? 0u : ((1u << (tot - lo)) - 1u));
        }
        for (int i = 0; i < tot; i++) {
            if ((keep[i >> 5] >> (i & 31)) & 1u) {
                for (int w = 0; w < nw; w++) keep[w] &= ~sup[i * 16 + w];
            }
        }
        #pragma unroll
        for (int w = 0; w < 16; w++) s_keep[w] = keep[w];
    }
    __syncthreads();                                              // B5

    // push kept keys + kept-score histogram
    for (int i = t; i < CAPC; i += 256) {
        bool kp = (i < tot) && ((s_keep[i >> 5] >> (i & 31)) & 1u);
        unsigned msk = __ballot_sync(full, kp);
        int base = 0;
        if (lane == 0 && msk) base = atomicAdd(&g_fcnt, __popc(msk));
        base = __shfl_sync(full, base, 0);
        if (kp) {
            g_fkey[base + __popc(msk & ((1u << lane) - 1u))] = skey[i];
            unsigned sb = ~(unsigned)(skey[i] >> 32);
            unsigned b = (sb - BITS04) >> 12;
            if (b >= BINS) b = BINS - 1;
            atomicAdd(&g_hist2[b], 1);
        }
    }
}

// ---------------- K8: threshold + rank-selection + write ----------------
__global__ void __launch_bounds__(1024) k8_final(const float* __restrict__ pred,
                                                 float* __restrict__ out) {
    __shared__ unsigned long long fk[FCAP];
    __shared__ int chunk[128];
    __shared__ int s_T2, s_cnt;
    int t = threadIdx.x, lane = t & 31;

    if (t < 128) {
        int s = 0;
        for (int b = t * 32; b < t * 32 + 32; b++) s += g_hist2[b];
        chunk[t] = s;
    }
    if (t == 0) s_cnt = 0;
    __syncthreads();
    if (t == 0) {
        int cum = 0, T2 = 0; bool found = false;
        for (int c = 127; c >= 0 && !found; c--) {
            if (cum + chunk[c] >= MAXDET) {
                for (int b = c * 32 + 31; b >= c * 32; b--) {
                    if (cum + g_hist2[b] >= MAXDET) { T2 = b; found = true; break; }
                    cum += g_hist2[b];
                }
            } else cum += chunk[c];
        }
        s_T2 = found ? T2 : 0;
    }
    __syncthreads();

    int K = min(g_fcnt, TOPK + 256);
    int T2 = s_T2;
    int Kr = (K + 31) & ~31;
    for (int i = t; i < Kr; i += 1024) {
        bool take = false;
        unsigned long long key = PADKEY;
        if (i < K) {
            key = g_fkey[i];
            unsigned sb = ~(unsigned)(key >> 32);
            unsigned b = (sb - BITS04) >> 12;
            if (b >= BINS) b = BINS - 1;
            take = ((int)b >= T2);
        }
        unsigned msk = __ballot_sync(0xffffffffu, take);
        int base = 0;
        if (lane == 0 && msk) base = atomicAdd(&s_cnt, __popc(msk));
        base = __shfl_sync(0xffffffffu, base, 0);
        if (take) {
            int p = base + __popc(msk & ((1u << lane) - 1u));
            if (p < FCAP) fk[p] = key;
        }
    }
    __syncthreads();

    int m2 = min(s_cnt, FCAP);
    for (int i = t; i < m2; i += 1024) {
        unsigned long long key = fk[i];
        int r = 0;
        for (int j = 0; j < m2; j++) r += (fk[j] < key);
        if (r < MAXDET) {
            unsigned idx = (unsigned)key;
            float s = __uint_as_float(~(unsigned)(key >> 32));
            const float* p = pred + (size_t)idx * ROW;
            float x = p[0], y = p[1], w = p[2], h = p[3];
            float hw = __fmul_rn(w, 0.5f), hh = __fmul_rn(h, 0.5f);
            out[r * 6 + 0] = __fsub_rn(x, hw);
            out[r * 6 + 1] = __fsub_rn(y, hh);
            out[r * 6 + 2] = __fadd_rn(x, hw);
            out[r * 6 + 3] = __fadd_rn(y, hh);
            out[r * 6 + 4] = s;
            out[r * 6 + 5] = (float)g_cls[idx];
        }
    }
}

extern "C" void kernel_launch(void* const* d_in, const int* in_sizes, int n_in,
                              void* d_out, int out_size) {
    (void)in_sizes; (void)n_in; (void)out_size;
    const float* pred = (const float*)d_in[0];
    float* out = (float*)d_out;

    static int configured = 0;
    if (!configured) {
        cudaFuncSetAttribute(k1_score, cudaFuncAttributeMaxDynamicSharedMemorySize,
                             K1SMEM);
        cudaFuncSetAttribute(k5_nms, cudaFuncAttributeMaxDynamicSharedMemorySize,
                             K5SMEM);
        configured = 1;
    }

    k0_zero<<<24, 256>>>(out);
    k1_score<<<K1B, K1T, K1SMEM>>>(pred);
    k3_gather<<<(NBOX / 4 + 255) / 256, 256>>>();
    k5_nms<<<NC, 256, K5SMEM>>>(pred);
    k8_final<<<1, 1024>>>(pred, out);
}

// round 13
// speedup vs baseline: 1.3846x; 1.0545x over previous
#include <cuda_runtime.h>
#include <stdint.h>

#define NBOX   100800
#define NC     80
#define ROW    85
#define TOPK   4096
#define BINS   4096
#define CAPC   512
#define BCAP   1024
#define FCAP   2048
#define MAXDET 1000
#define CONF_T 0.4f
#define IOU_T  0.45f
#define MAXWH  7680.0f
#define BITS04 0x3ECCCCCDu
#define PADKEY 0xFFFFFFFFFFFFFFFFULL

// KA config: one 256-row chunk per block
#define CROWS  256
#define K1B    ((NBOX + CROWS - 1) / CROWS)      // 394
#define K1T    256
#define K1SMEM (CROWS * ROW * 4)                 // 87040 B -> 2 blocks/SM

// KB config
#define GRID2  80
#define NT2    512
// KB smem layout (bytes)
#define SM5_RAW  0                                // CAPC u64
#define SM5_KEY  4096
#define SM5_SBT  8192                             // BCAP u64
#define SM5_SX1  16384
#define SM5_SY1  18432
#define SM5_SX2  20480
#define SM5_SY2  22528
#define SM5_SAR  24576
#define SM5_SUP  26624                            // u32 [CAPC][16]
#define K5SMEM   (SM5_SUP + CAPC * 16 * 4)        // 59392 B (fk overlays at 0 in final phase)

__device__ float              g_score[NBOX];
__device__ unsigned char      g_cls[NBOX];
__device__ int                g_hist[BINS];       // zeroed by prev replay's KB tail
__device__ int                g_hist2[BINS];
__device__ int                g_tbin, g_need;
__device__ int                g_done;             // KA completion counter
__device__ int                g_done2;            // KB completion counter
__device__ int                g_ccount[NC];
__device__ unsigned long long g_ckey[NC * CAPC];
__device__ unsigned long long g_btbl[BCAP];
__device__ int                g_bcnt;
__device__ unsigned long long g_fkey[TOPK + 256];
__device__ int                g_fcnt;

// sense-reversing global barrier for KB (80 blocks, guaranteed co-resident)
__device__ int          g_bar_cnt = 0;
__device__ volatile int g_bar_gen = 0;            // monotone across replays; NEVER reset

__device__ __forceinline__ void gbar80() {
    __syncthreads();
    if (threadIdx.x == 0) {
        int gen = g_bar_gen;
        __threadfence();
        if (atomicAdd(&g_bar_cnt, 1) == GRID2 - 1) {
            g_bar_cnt = 0;
            __threadfence();
            g_bar_gen = gen + 1;
        } else {
            while (g_bar_gen == gen) { }
        }
        __threadfence();
    }
    __syncthreads();
}

// =================== KA: score + argmax + hist + threshold ===================
__global__ void __launch_bounds__(K1T, 2) k1_score(const float* __restrict__ pred) {
    extern __shared__ float srow[];               // CROWS*ROW floats
    __shared__ int s_last;
    __shared__ int chunk2[128];
    int t = threadIdx.x;
    int b0 = blockIdx.x * CROWS;
    int nrows = NBOX - b0; if (nrows > CROWS) nrows = CROWS;
    int nf4 = (nrows * ROW) >> 2;                 // nrows % 4 == 0 -> exact
    const float4* src = (const float4*)(pred + (size_t)b0 * ROW);
    float4* dst = (float4*)srow;
    #pragma unroll 4
    for (int i = t; i < nf4; i += K1T) dst[i] = src[i];
    __syncthreads();

    if (t < nrows) {
        const float* p = srow + t * ROW;
        float obj = p[4];
        // pass 1: value max via fmaxf chain (4-cyc ops, low live-register count)
        float best = __fmul_rn(p[5], obj);
        #pragma unroll
        for (int cc = 1; cc < NC; cc++)
            best = fmaxf(best, __fmul_rn(p[5 + cc], obj));
        // pass 2: first index achieving max (recompute == best; ffs)
        unsigned m0 = 0, m1 = 0, m2v = 0;
        #pragma unroll
        for (int cc = 0; cc < 32; cc++)
            if (__fmul_rn(p[5 + cc], obj) == best) m0 |= (1u << cc);
        #pragma unroll
        for (int cc = 32; cc < 64; cc++)
            if (__fmul_rn(p[5 + cc], obj) == best) m1 |= (1u << (cc - 32));
        #pragma unroll
        for (int cc = 64; cc < 80; cc++)
            if (__fmul_rn(p[5 + cc], obj) == best) m2v |= (1u << (cc - 64));
        int bc = m0 ? (__ffs(m0) - 1) : (m1 ? (31 + __ffs(m1)) : (63 + __ffs(m2v)));

        int gi = b0 + t;
        g_score[gi] = best;
        g_cls[gi]   = (unsigned char)bc;
        if (best > CONF_T) {
            unsigned b = (__float_as_uint(best) - BITS04) >> 12;
            if (b >= BINS) b = BINS - 1;
            atomicAdd(&g_hist[b], 1);             // ~150 atomics/block, 4096 addrs
        }
    }
    __syncthreads();
    if (t == 0) {
        __threadfence();
        s_last = (atomicAdd(&g_done, 1) == K1B - 1);
    }
    __syncthreads();
    if (s_last) {
        if (t < 128) {
            int s = 0;
            for (int b = t * 32; b < t * 32 + 32; b++) s += g_hist[b];
            chunk2[t] = s;
        }
        __syncthreads();
        if (t == 0) {
            int cum = 0, tb = 0, A = 0; bool found = false;
            for (int c = 127; c >= 0 && !found; c--) {
                if (cum + chunk2[c] >= TOPK) {
                    for (int b = c * 32 + 31; b >= c * 32; b--) {
                        if (cum + g_hist[b] >= TOPK) { tb = b; A = cum; found = true; break; }
                        cum += g_hist[b];
                    }
                } else cum += chunk2[c];
            }
            if (!found) { tb = 0; A = cum - g_hist[0]; }
            g_tbin = tb;
            g_need = TOPK - A;
        }
    }
}

// ============ KB: gather + gbar + per-class NMS + final + scratch-reset ======
__global__ void __launch_bounds__(NT2) k2_nms(const float* __restrict__ pred,
                                              float* __restrict__ out) {
    extern __shared__ char sm5[];
    unsigned long long* raw  = (unsigned long long*)(sm5 + SM5_RAW);
    unsigned long long* skey = (unsigned long long*)(sm5 + SM5_KEY);
    unsigned long long* sbt  = (unsigned long long*)(sm5 + SM5_SBT);
    float* sx1 = (float*)(sm5 + SM5_SX1);
    float* sy1 = (float*)(sm5 + SM5_SY1);
    float* sx2 = (float*)(sm5 + SM5_SX2);
    float* sy2 = (float*)(sm5 + SM5_SY2);
    float* sar = (float*)(sm5 + SM5_SAR);
    unsigned* sup = (unsigned*)(sm5 + SM5_SUP);
    __shared__ int s_extra;
    __shared__ unsigned s_keep[16];
    __shared__ int s_last2;

    const unsigned full = 0xffffffffu;
    int t = threadIdx.x, lane = t & 31, wid = t >> 5;
    int bid = blockIdx.x;

    // -------- Phase 1: cooperative gather (old k3) --------
    {
        int tb = g_tbin;
        for (int q = bid * NT2 + t; q < NBOX / 4; q += GRID2 * NT2) {
            float4 s4 = *(const float4*)(g_score + q * 4);
            float sv[4] = { s4.x, s4.y, s4.z, s4.w };
            #pragma unroll
            for (int u = 0; u < 4; u++) {
                float s = sv[u];
                if (s > CONF_T) {
                    unsigned sb = __float_as_uint(s);
                    unsigned b  = (sb - BITS04) >> 12;
                    if (b >= BINS) b = BINS - 1;
                    if ((int)b >= tb) {
                        int i = q * 4 + u;
                        unsigned long long key =
                            ((unsigned long long)(~sb) << 32) | (unsigned)i;
                        if ((int)b > tb) {
                            int c = g_cls[i];
                            int p = atomicAdd(&g_ccount[c], 1);
                            if (p < CAPC) g_ckey[c * CAPC + p] = key;
                        } else {
                            int p = atomicAdd(&g_bcnt, 1);
                            if (p < BCAP) g_btbl[p] = key;
                        }
                    }
                }
            }
        }
    }
    gbar80();

    // -------- Phase 2: per-class NMS (class == bid) --------
    {
        int myc = bid;
        int cnt = min(g_ccount[myc], CAPC);
        int m = min(g_bcnt, BCAP);
        int need = g_need;

        if (t == 0) s_extra = 0;
        for (int i = t; i < m; i += NT2) sbt[i] = g_btbl[i];
        for (int i = t; i < cnt; i += NT2) raw[i] = g_ckey[myc * CAPC + i];
        __syncthreads();

        for (int e = t; e < m; e += NT2) {
            unsigned long long k = sbt[e];
            int r = 0;
            for (int j = 0; j < m; j++) r += (sbt[j] < k);
            if (r < need) {
                unsigned idx = (unsigned)k;
                if (g_cls[idx] == (unsigned char)myc) {
                    int p = atomicAdd(&s_extra, 1);
                    if (cnt + p < CAPC) raw[cnt + p] = k;
                }
            }
        }
        __syncthreads();

        int tot = cnt + s_extra;
        if (tot > CAPC) tot = CAPC;
        float off = __fmul_rn((float)myc, MAXWH);

        // rank (keys unique) -> scatter key + coords to sorted position
        for (int i = t; i < tot; i += NT2) {
            unsigned long long k = raw[i];
            int r = 0;
            for (int j = 0; j < tot; j++) r += (raw[j] < k);
            skey[r] = k;
            unsigned idx = (unsigned)k;
            const float* p = pred + (size_t)idx * ROW;
            float x = p[0], y = p[1], w = p[2], h = p[3];
            float hw = __fmul_rn(w, 0.5f), hh = __fmul_rn(h, 0.5f);
            float b0 = __fsub_rn(x, hw), b1 = __fsub_rn(y, hh);
            float b2 = __fadd_rn(x, hw), b3 = __fadd_rn(y, hh);
            float q0 = __fadd_rn(b0, off), q1 = __fadd_rn(b1, off);
            float q2 = __fadd_rn(b2, off), q3 = __fadd_rn(b3, off);
            sx1[r] = q0; sy1[r] = q1; sx2[r] = q2; sy2[r] = q3;
            sar[r] = __fmul_rn(__fsub_rn(q2, q0), __fsub_rn(q3, q1));
        }
        __syncthreads();

        // suppression matrix via warp ballots
        int nw = (tot + 31) >> 5;
        for (int r = wid; r < tot; r += NT2 / 32) {
            float x1 = sx1[r], y1 = sy1[r], x2 = sx2[r], y2 = sy2[r], a = sar[r];
            for (int w = 0; w < nw; w++) {
                int j = w * 32 + lane;
                bool s = false;
                if (j < tot && j > r) {
                    float ltx = fmaxf(sx1[j], x1);
                    float lty = fmaxf(sy1[j], y1);
                    float rbx = fminf(sx2[j], x2);
                    float rby = fminf(sy2[j], y2);
                    float ww  = fmaxf(__fsub_rn(rbx, ltx), 0.0f);
                    float hh  = fmaxf(__fsub_rn(rby, lty), 0.0f);
                    float inter = __fmul_rn(ww, hh);
                    float den = __fadd_rn(__fsub_rn(__fadd_rn(a, sar[j]), inter), 1e-9f);
                    s = __fdiv_rn(inter, den) > IOU_T;
                }
                unsigned msk = __ballot_sync(full, s);
                if (lane == 0) sup[r * 16 + w] = msk;
            }
        }
        __syncthreads();

        // greedy bit recurrence (reference fori_loop semantics)
        if (t == 0) {
            unsigned keep[16];
            #pragma unroll
            for (int w = 0; w < 16; w++) {
                int lo = w * 32;
                keep[w] = (tot >= lo + 32) ? 0xffffffffu
                        : (tot <= lo ? 0u : ((1u << (tot - lo)) - 1u));
            }
            for (int i = 0; i < tot; i++) {
                if ((keep[i >> 5] >> (i & 31)) & 1u) {
                    for (int w = 0; w < nw; w++) keep[w] &= ~sup[i * 16 + w];
                }
            }
            #pragma unroll
            for (int w = 0; w < 16; w++) s_keep[w] = keep[w];
        }
        __syncthreads();

        // push kept keys + kept-score histogram
        for (int i = t; i < CAPC; i += NT2) {
            bool kp = (i < tot) && ((s_keep[i >> 5] >> (i & 31)) & 1u);
            unsigned msk = __ballot_sync(full, kp);
            int base = 0;
            if (lane == 0 && msk) base = atomicAdd(&g_fcnt, __popc(msk));
            base = __shfl_sync(full, base, 0);
            if (kp) {
                g_fkey[base + __popc(msk & ((1u << lane) - 1u))] = skey[i];
                unsigned sb = ~(unsigned)(skey[i] >> 32);
                unsigned b = (sb - BITS04) >> 12;
                if (b >= BINS) b = BINS - 1;
                atomicAdd(&g_hist2[b], 1);
            }
        }
    }

    // -------- Phase 3: last-done block finalizes + resets scratch --------
    __syncthreads();
    if (t == 0) {
        __threadfence();
        s_last2 = (atomicAdd(&g_done2, 1) == GRID2 - 1);
    }
    __syncthreads();
    if (s_last2) {
        unsigned long long* fk = (unsigned long long*)sm5;   // 16 KB overlay
        __shared__ int chunk[128];
        __shared__ int s_T2, s_cnt;

        if (t < 128) {
            int s = 0;
            for (int b = t * 32; b < t * 32 + 32; b++) s += g_hist2[b];
            chunk[t] = s;
        }
        if (t == 0) s_cnt = 0;
        __syncthreads();
        if (t == 0) {
            int cum = 0, T2 = 0; bool found = false;
            for (int c = 127; c >= 0 && !found; c--) {
                if (cum + chunk[c] >= MAXDET) {
                    for (int b = c * 32 + 31; b >= c * 32; b--) {
                        if (cum + g_hist2[b] >= MAXDET) { T2 = b; found = true; break; }
                        cum += g_hist2[b];
                    }
                } else cum += chunk[c];
            }
            s_T2 = found ? T2 : 0;
        }
        __syncthreads();

        int K = min(g_fcnt, TOPK + 256);
        int T2 = s_T2;
        int Kr = (K + 31) & ~31;
        for (int i = t; i < Kr; i += NT2) {
            bool take = false;
            unsigned long long key = PADKEY;
            if (i < K) {
                key = g_fkey[i];
                unsigned sb = ~(unsigned)(key >> 32);
                unsigned b = (sb - BITS04) >> 12;
                if (b >= BINS) b = BINS - 1;
                take = ((int)b >= T2);
            }
            unsigned msk = __ballot_sync(full, take);
            int base = 0;
            if (lane == 0 && msk) base = atomicAdd(&s_cnt, __popc(msk));
            base = __shfl_sync(full, base, 0);
            if (take) {
                int p = base + __popc(msk & ((1u << lane) - 1u));
                if (p < FCAP) fk[p] = key;
            }
        }
        __syncthreads();

        int m2 = min(s_cnt, FCAP);
        for (int i = t; i < m2; i += NT2) {
            unsigned long long key = fk[i];
            int r = 0;
            for (int j = 0; j < m2; j++) r += (fk[j] < key);   // exact rank
            if (r < MAXDET) {
                unsigned idx = (unsigned)key;
                float s = __uint_as_float(~(unsigned)(key >> 32));
                const float* p = pred + (size_t)idx * ROW;
                float x = p[0], y = p[1], w = p[2], h = p[3];
                float hw = __fmul_rn(w, 0.5f), hh = __fmul_rn(h, 0.5f);
                out[r * 6 + 0] = __fsub_rn(x, hw);
                out[r * 6 + 1] = __fsub_rn(y, hh);
                out[r * 6 + 2] = __fadd_rn(x, hw);
                out[r * 6 + 3] = __fadd_rn(y, hh);
                out[r * 6 + 4] = s;
                out[r * 6 + 5] = (float)g_cls[idx];
            }
        }
        // rows beyond kept count are zero
        for (int r = m2 + t; r < MAXDET; r += NT2) {
            out[r * 6 + 0] = 0.0f; out[r * 6 + 1] = 0.0f; out[r * 6 + 2] = 0.0f;
            out[r * 6 + 3] = 0.0f; out[r * 6 + 4] = 0.0f; out[r * 6 + 5] = 0.0f;
        }

        // reset ALL scratch for the next graph replay (g_bar_gen stays monotone)
        for (int i = t; i < BINS; i += NT2) { g_hist[i] = 0; g_hist2[i] = 0; }
        for (int i = t; i < NC; i += NT2) g_ccount[i] = 0;
        if (t == 0) { g_bcnt = 0; g_fcnt = 0; g_done = 0; g_done2 = 0; }
    }
}

extern "C" void kernel_launch(void* const* d_in, const int* in_sizes, int n_in,
                              void* d_out, int out_size) {
    (void)in_sizes; (void)n_in; (void)out_size;
    const float* pred = (const float*)d_in[0];
    float* out = (float*)d_out;

    static int configured = 0;
    if (!configured) {
        cudaFuncSetAttribute(k1_score, cudaFuncAttributeMaxDynamicSharedMemorySize,
                             K1SMEM);
        cudaFuncSetAttribute(k2_nms, cudaFuncAttributeMaxDynamicSharedMemorySize,
                             K5SMEM);
        configured = 1;
    }

    k1_score<<<K1B, K1T, K1SMEM>>>(pred);
    k2_nms<<<GRID2, NT2, K5SMEM>>>(pred, out);
}

// round 16
// speedup vs baseline: 1.4539x; 1.0501x over previous
#include <cuda_runtime.h>
#include <stdint.h>

#define NBOX   100800
#define NC     80
#define ROW    85
#define TOPK   4096
#define BINS   4096
#define CAPC   512
#define BCAP   1024
#define FCAP   2048
#define MAXDET 1000
#define CONF_T 0.4f
#define IOU_T  0.45f
#define MAXWH  7680.0f
#define BITS04 0x3ECCCCCDu
#define PADKEY 0xFFFFFFFFFFFFFFFFULL

// KA config: one 256-row chunk per block
#define CROWS  256
#define K1B    ((NBOX + CROWS - 1) / CROWS)      // 394
#define K1T    256
#define K1SMEM (CROWS * ROW * 4)                 // 87040 B -> 2 blocks/SM

// KB config
#define GRID2  80
#define NT2    512
// KB smem layout (bytes); sup gets CAPC+1 rows so prefetch row `tot` is in-bounds
#define SM5_RAW  0                                // CAPC u64
#define SM5_KEY  4096
#define SM5_SBT  8192                             // BCAP u64
#define SM5_SX1  16384
#define SM5_SY1  18432
#define SM5_SX2  20480
#define SM5_SY2  22528
#define SM5_SAR  24576
#define SM5_SUP  26624                            // u32 [CAPC+1][16]
#define K5SMEM   (SM5_SUP + (CAPC + 1) * 16 * 4) // 59456 B

__device__ float              g_score[NBOX];
__device__ unsigned char      g_cls[NBOX];
__device__ int                g_hist[BINS];       // zeroed by prev replay's K8
__device__ int                g_hist2[BINS];
__device__ int                g_tbin, g_need;
__device__ int                g_done;             // KA completion counter
__device__ int                g_ccount[NC];
__device__ unsigned long long g_ckey[NC * CAPC];
__device__ unsigned long long g_btbl[BCAP];
__device__ int                g_bcnt;
__device__ unsigned long long g_fkey[TOPK + 256];
__device__ int                g_fcnt;

// sense-reversing global barrier for KB (80 blocks <= 148 SMs -> co-resident)
__device__ int          g_bar_cnt = 0;
__device__ volatile int g_bar_gen = 0;            // monotone across replays; NEVER reset

__device__ __forceinline__ void gbar80() {
    __syncthreads();
    if (threadIdx.x == 0) {
        int gen = g_bar_gen;
        __threadfence();
        if (atomicAdd(&g_bar_cnt, 1) == GRID2 - 1) {
            g_bar_cnt = 0;
            __threadfence();
            g_bar_gen = gen + 1;
        } else {
            while (g_bar_gen == gen) { }
        }
        __threadfence();
    }
    __syncthreads();
}

// =================== KA: score + argmax + hist + threshold ===================
__global__ void __launch_bounds__(K1T, 2) k1_score(const float* __restrict__ pred) {
    extern __shared__ float srow[];
    __shared__ int s_last;
    __shared__ int chunk2[128];
    int t = threadIdx.x;
    int b0 = blockIdx.x * CROWS;
    int nrows = NBOX - b0; if (nrows > CROWS) nrows = CROWS;
    int nf4 = (nrows * ROW) >> 2;
    const float4* src = (const float4*)(pred + (size_t)b0 * ROW);
    float4* dst = (float4*)srow;
    #pragma unroll 4
    for (int i = t; i < nf4; i += K1T) dst[i] = src[i];
    __syncthreads();

    if (t < nrows) {
        const float* p = srow + t * ROW;
        float obj = p[4];
        float best = __fmul_rn(p[5], obj);
        #pragma unroll
        for (int cc = 1; cc < NC; cc++)
            best = fmaxf(best, __fmul_rn(p[5 + cc], obj));
        unsigned m0 = 0, m1 = 0, m2v = 0;
        #pragma unroll
        for (int cc = 0; cc < 32; cc++)
            if (__fmul_rn(p[5 + cc], obj) == best) m0 |= (1u << cc);
        #pragma unroll
        for (int cc = 32; cc < 64; cc++)
            if (__fmul_rn(p[5 + cc], obj) == best) m1 |= (1u << (cc - 32));
        #pragma unroll
        for (int cc = 64; cc < 80; cc++)
            if (__fmul_rn(p[5 + cc], obj) == best) m2v |= (1u << (cc - 64));
        int bc = m0 ? (__ffs(m0) - 1) : (m1 ? (31 + __ffs(m1)) : (63 + __ffs(m2v)));

        int gi = b0 + t;
        g_score[gi] = best;
        g_cls[gi]   = (unsigned char)bc;
        if (best > CONF_T) {
            unsigned b = (__float_as_uint(best) - BITS04) >> 12;
            if (b >= BINS) b = BINS - 1;
            atomicAdd(&g_hist[b], 1);
        }
    }
    __syncthreads();
    if (t == 0) {
        __threadfence();
        s_last = (atomicAdd(&g_done, 1) == K1B - 1);
    }
    __syncthreads();
    if (s_last) {
        if (t < 128) {
            int s = 0;
            for (int b = t * 32; b < t * 32 + 32; b++) s += g_hist[b];
            chunk2[t] = s;
        }
        __syncthreads();
        if (t == 0) {
            int cum = 0, tb = 0, A = 0; bool found = false;
            for (int c = 127; c >= 0 && !found; c--) {
                if (cum + chunk2[c] >= TOPK) {
                    for (int b = c * 32 + 31; b >= c * 32; b--) {
                        if (cum + g_hist[b] >= TOPK) { tb = b; A = cum; found = true; break; }
                        cum += g_hist[b];
                    }
                } else cum += chunk2[c];
            }
            if (!found) { tb = 0; A = cum - g_hist[0]; }
            g_tbin = tb;
            g_need = TOPK - A;
        }
    }
}

// =================== KB: gather + gbar + per-class NMS ===================
__global__ void __launch_bounds__(NT2) k2_nms(const float* __restrict__ pred) {
    extern __shared__ char sm5[];
    unsigned long long* raw  = (unsigned long long*)(sm5 + SM5_RAW);
    unsigned long long* skey = (unsigned long long*)(sm5 + SM5_KEY);
    unsigned long long* sbt  = (unsigned long long*)(sm5 + SM5_SBT);
    float* sx1 = (float*)(sm5 + SM5_SX1);
    float* sy1 = (float*)(sm5 + SM5_SY1);
    float* sx2 = (float*)(sm5 + SM5_SX2);
    float* sy2 = (float*)(sm5 + SM5_SY2);
    float* sar = (float*)(sm5 + SM5_SAR);
    unsigned* sup = (unsigned*)(sm5 + SM5_SUP);
    __shared__ int s_extra;
    __shared__ unsigned s_keep[16];

    const unsigned full = 0xffffffffu;
    int t = threadIdx.x, lane = t & 31, wid = t >> 5;
    int bid = blockIdx.x;

    // -------- Phase 1: cooperative gather --------
    {
        int tb = g_tbin;
        for (int q = bid * NT2 + t; q < NBOX / 4; q += GRID2 * NT2) {
            float4 s4 = *(const float4*)(g_score + q * 4);
            float sv[4] = { s4.x, s4.y, s4.z, s4.w };
            #pragma unroll
            for (int u = 0; u < 4; u++) {
                float s = sv[u];
                if (s > CONF_T) {
                    unsigned sb = __float_as_uint(s);
                    unsigned b  = (sb - BITS04) >> 12;
                    if (b >= BINS) b = BINS - 1;
                    if ((int)b >= tb) {
                        int i = q * 4 + u;
                        unsigned long long key =
                            ((unsigned long long)(~sb) << 32) | (unsigned)i;
                        if ((int)b > tb) {
                            int c = g_cls[i];
                            int p = atomicAdd(&g_ccount[c], 1);
                            if (p < CAPC) g_ckey[c * CAPC + p] = key;
                        } else {
                            int p = atomicAdd(&g_bcnt, 1);
                            if (p < BCAP) g_btbl[p] = key;
                        }
                    }
                }
            }
        }
    }
    gbar80();

    // -------- Phase 2: per-class NMS (class == bid) --------
    int myc = bid;
    int cnt = min(g_ccount[myc], CAPC);
    int m = min(g_bcnt, BCAP);
    int need = g_need;

    if (t == 0) s_extra = 0;
    for (int i = t; i < m; i += NT2) sbt[i] = g_btbl[i];
    for (int i = t; i < cnt; i += NT2) raw[i] = g_ckey[myc * CAPC + i];
    __syncthreads();

    for (int e = t; e < m; e += NT2) {
        unsigned long long k = sbt[e];
        int r = 0;
        for (int j = 0; j < m; j++) r += (sbt[j] < k);
        if (r < need) {
            unsigned idx = (unsigned)k;
            if (g_cls[idx] == (unsigned char)myc) {
                int p = atomicAdd(&s_extra, 1);
                if (cnt + p < CAPC) raw[cnt + p] = k;
            }
        }
    }
    __syncthreads();

    int tot = cnt + s_extra;
    if (tot > CAPC) tot = CAPC;
    float off = __fmul_rn((float)myc, MAXWH);

    // rank-scatter (keys unique) -> sorted position
    for (int i = t; i < tot; i += NT2) {
        unsigned long long k = raw[i];
        int r = 0;
        for (int j = 0; j < tot; j++) r += (raw[j] < k);
        skey[r] = k;
        unsigned idx = (unsigned)k;
        const float* p = pred + (size_t)idx * ROW;
        float x = p[0], y = p[1], w = p[2], h = p[3];
        float hw = __fmul_rn(w, 0.5f), hh = __fmul_rn(h, 0.5f);
        float b0 = __fsub_rn(x, hw), b1 = __fsub_rn(y, hh);
        float b2 = __fadd_rn(x, hw), b3 = __fadd_rn(y, hh);
        float q0 = __fadd_rn(b0, off), q1 = __fadd_rn(b1, off);
        float q2 = __fadd_rn(b2, off), q3 = __fadd_rn(b3, off);
        sx1[r] = q0; sy1[r] = q1; sx2[r] = q2; sy2[r] = q3;
        sar[r] = __fmul_rn(__fsub_rn(q2, q0), __fsub_rn(q3, q1));
    }
    __syncthreads();

    // suppression matrix via warp ballots (row-major, bits j>r)
    int nw = (tot + 31) >> 5;
    for (int r = wid; r < tot; r += NT2 / 32) {
        float x1 = sx1[r], y1 = sy1[r], x2 = sx2[r], y2 = sy2[r], a = sar[r];
        for (int w = 0; w < nw; w++) {
            int j = w * 32 + lane;
            bool s = false;
            if (j < tot && j > r) {
                float ltx = fmaxf(sx1[j], x1);
                float lty = fmaxf(sy1[j], y1);
                float rbx = fminf(sx2[j], x2);
                float rby = fminf(sy2[j], y2);
                float ww  = fmaxf(__fsub_rn(rbx, ltx), 0.0f);
                float hh  = fmaxf(__fsub_rn(rby, lty), 0.0f);
                float inter = __fmul_rn(ww, hh);
                float den = __fadd_rn(__fsub_rn(__fadd_rn(a, sar[j]), inter), 1e-9f);
                s = __fdiv_rn(inter, den) > IOU_T;
            }
            unsigned msk = __ballot_sync(full, s);
            if (lane == 0) sup[r * 16 + w] = msk;
        }
    }
    // zero the prefetch row (row index == tot) for the pipelined greedy
    if (t < 16) sup[tot * 16 + t] = 0;
    __syncthreads();

    // greedy bit recurrence; fast pipelined path for tot<=64 (the common case)
    if (t == 0) {
        if (tot <= 64) {
            unsigned k0 = (tot >= 32) ? 0xffffffffu : ((tot > 0) ? ((1u << tot) - 1u) : 0u);
            unsigned k1 = (tot >= 64) ? 0xffffffffu
                        : (tot > 32 ? ((1u << (tot - 32)) - 1u) : 0u);
            unsigned s0 = sup[0], s1 = sup[1];
            for (int i = 0; i < tot; i++) {
                unsigned n0 = sup[(i + 1) * 16 + 0];      // prefetch next row
                unsigned n1 = sup[(i + 1) * 16 + 1];
                bool kb = (i < 32) ? ((k0 >> i) & 1u) : ((k1 >> (i - 32)) & 1u);
                if (kb) { k0 &= ~s0; k1 &= ~s1; }
                s0 = n0; s1 = n1;
            }
            s_keep[0] = k0; s_keep[1] = k1;
            #pragma unroll
            for (int w = 2; w < 16; w++) s_keep[w] = 0;
        } else {
            unsigned keep[16];
            #pragma unroll
            for (int w = 0; w < 16; w++) {
                int lo = w * 32;
                keep[w] = (tot >= lo + 32) ? 0xffffffffu
                        : (tot <= lo ? 0u : ((1u << (tot - lo)) - 1u));
            }
            for (int i = 0; i < tot; i++) {
                if ((keep[i >> 5] >> (i & 31)) & 1u) {
                    for (int w = 0; w < nw; w++) keep[w] &= ~sup[i * 16 + w];
                }
            }
            #pragma unroll
            for (int w = 0; w < 16; w++) s_keep[w] = keep[w];
        }
    }
    __syncthreads();

    // push kept keys + kept-score histogram
    for (int i = t; i < CAPC; i += NT2) {
        bool kp = (i < tot) && ((s_keep[i >> 5] >> (i & 31)) & 1u);
        unsigned msk = __ballot_sync(full, kp);
        int base = 0;
        if (lane == 0 && msk) base = atomicAdd(&g_fcnt, __popc(msk));
        base = __shfl_sync(full, base, 0);
        if (kp) {
            g_fkey[base + __popc(msk & ((1u << lane) - 1u))] = skey[i];
            unsigned sb = ~(unsigned)(skey[i] >> 32);
            unsigned b = (sb - BITS04) >> 12;
            if (b >= BINS) b = BINS - 1;
            atomicAdd(&g_hist2[b], 1);
        }
    }
}

// =================== K8: finalize + write + scratch reset ===================
__global__ void __launch_bounds__(1024) k8_final(const float* __restrict__ pred,
                                                 float* __restrict__ out) {
    __shared__ unsigned long long fk[FCAP];
    __shared__ int chunk[128];
    __shared__ int s_T2, s_cnt;
    int t = threadIdx.x, lane = t & 31;

    if (t < 128) {
        int s = 0;
        for (int b = t * 32; b < t * 32 + 32; b++) s += g_hist2[b];
        chunk[t] = s;
    }
    if (t == 0) s_cnt = 0;
    __syncthreads();
    if (t == 0) {
        int cum = 0, T2 = 0; bool found = false;
        for (int c = 127; c >= 0 && !found; c--) {
            if (cum + chunk[c] >= MAXDET) {
                for (int b = c * 32 + 31; b >= c * 32; b--) {
                    if (cum + g_hist2[b] >= MAXDET) { T2 = b; found = true; break; }
                    cum += g_hist2[b];
                }
            } else cum += chunk[c];
        }
        s_T2 = found ? T2 : 0;
    }
    __syncthreads();

    int K = min(g_fcnt, TOPK + 256);
    int T2 = s_T2;
    int Kr = (K + 31) & ~31;
    for (int i = t; i < Kr; i += 1024) {
        bool take = false;
        unsigned long long key = PADKEY;
        if (i < K) {
            key = g_fkey[i];
            unsigned sb = ~(unsigned)(key >> 32);
            unsigned b = (sb - BITS04) >> 12;
            if (b >= BINS) b = BINS - 1;
            take = ((int)b >= T2);
        }
        unsigned msk = __ballot_sync(0xffffffffu, take);
        int base = 0;
        if (lane == 0 && msk) base = atomicAdd(&s_cnt, __popc(msk));
        base = __shfl_sync(0xffffffffu, base, 0);
        if (take) {
            int p = base + __popc(msk & ((1u << lane) - 1u));
            if (p < FCAP) fk[p] = key;
        }
    }
    __syncthreads();

    int m2 = min(s_cnt, FCAP);
    for (int i = t; i < m2; i += 1024) {
        unsigned long long key = fk[i];
        int r = 0;
        for (int j = 0; j < m2; j++) r += (fk[j] < key);   // exact rank, unique keys
        if (r < MAXDET) {
            unsigned idx = (unsigned)key;
            float s = __uint_as_float(~(unsigned)(key >> 32));
            const float* p = pred + (size_t)idx * ROW;
            float x = p[0], y = p[1], w = p[2], h = p[3];
            float hw = __fmul_rn(w, 0.5f), hh = __fmul_rn(h, 0.5f);
            out[r * 6 + 0] = __fsub_rn(x, hw);
            out[r * 6 + 1] = __fsub_rn(y, hh);
            out[r * 6 + 2] = __fadd_rn(x, hw);
            out[r * 6 + 3] = __fadd_rn(y, hh);
            out[r * 6 + 4] = s;
            out[r * 6 + 5] = (float)g_cls[idx];
        }
    }
    // rows beyond kept count are zero (d_out is poisoned before timing)
    for (int r = m2 + t; r < MAXDET; r += 1024) {
        out[r * 6 + 0] = 0.0f; out[r * 6 + 1] = 0.0f; out[r * 6 + 2] = 0.0f;
        out[r * 6 + 3] = 0.0f; out[r * 6 + 4] = 0.0f; out[r * 6 + 5] = 0.0f;
    }

    // reset ALL scratch for the next graph replay (g_bar_gen stays monotone)
    for (int i = t; i < BINS; i += 1024) { g_hist[i] = 0; g_hist2[i] = 0; }
    for (int i = t; i < NC; i += 1024) g_ccount[i] = 0;
    if (t == 0) { g_bcnt = 0; g_fcnt = 0; g_done = 0; }
}

extern "C" void kernel_launch(void* const* d_in, const int* in_sizes, int n_in,
                              void* d_out, int out_size) {
    (void)in_sizes; (void)n_in; (void)out_size;
    const float* pred = (const float*)d_in[0];
    float* out = (float*)d_out;

    static int configured = 0;
    if (!configured) {
        cudaFuncSetAttribute(k1_score, cudaFuncAttributeMaxDynamicSharedMemorySize,
                             K1SMEM);
        cudaFuncSetAttribute(k2_nms, cudaFuncAttributeMaxDynamicSharedMemorySize,
                             K5SMEM);
        configured = 1;
    }

    k1_score<<<K1B, K1T, K1SMEM>>>(pred);
    k2_nms<<<GRID2, NT2, K5SMEM>>>(pred);
    k8_final<<<1, 1024>>>(pred, out);
}